// round 16
// baseline (speedup 1.0000x reference)
#include <cuda_runtime.h>
#include <cuda_bf16.h>
#include <stdint.h>

#define NPW 16
#define M   64
#define NT  1024           // 32 warps, 8/SMSP
#define NW  (NT / 32)
#define NG  16             // row groups for m^2 phases: 16 groups x 4 rows
#define OBJ 10
#define DSTR 68            // dsT row stride (floats)
#define NSLOT 528          // 32*33/2 2x2 blocks (incl diagonal blocks)

#define MAGIC 12582912.0f  // 1.5*2^23; bits(MAGIC + m) = 0x4B400000 + m

// Dynamic shared memory layout (bytes); all offsets 16B-aligned
#define OFF_DST   0u          // dsT[j*68 + l], pre-scaled by 16, in [0,16)  (17408)
#define OFF_SIM   17408u      // (16384)
#define OFF_AM    33792u      // (16384)
#define OFF_T03   50176u      // float4[19*16]  f0 .xy / f3 .zw       (4864)
#define OFF_T14   55040u      // float4[19*16]  f1 .xy / f4 .zw       (4864)
#define OFF_T6    62336u      // float2[19*16]                        (2432)
#define OFF_T5    64768u      // float2[19*16]                        (2432)
#define OFF_T7    67200u      // float2[19] + pad                     (160)
#define OFF_TAB   67360u      // float2[8*17] (csum, w_next)          (1088)
#define OFF_ATT   68448u
#define OFF_AREA  68704u
#define OFF_BX1   68960u
#define OFF_BY1   69216u
#define OFF_BX2   69472u
#define OFF_BY2   69728u
#define OFF_PART  69984u      // NG*64*4 = 4096
#define OFF_RINV  74080u
#define OFF_WRA   74336u      // 32 floats
#define OFF_WRB   74464u      // 32 floats
#define SMEM_TOTAL 74592u

// Protected magic-add: __fadd_rn is never merged/reassociated, so fast-math
// cannot refold bias constants into MAGIC (the R5/R6 bug).
__device__ __forceinline__ uint32_t magic_bits(float t) {
    return __float_as_uint(__fadd_rn(t, MAGIC));
}

// Fused-table entry for slot = n+1 (n = -1..17):
//   val(x) = T0 + (16x)*T1 on segment n, T0 = csum[n] - n*w_next, T1 = w_next.
//   slot 0 (n=-1) encodes the reference's x<0 branch.
__device__ __forceinline__ float2 fused_entry(const float2* __restrict__ t, int slot) {
    if (slot == 0) {
        float cs0 = t[0].x, w1 = t[0].y;
        return make_float2(cs0 + w1, w1);
    }
    int n = slot - 1; if (n > 16) n = 16;
    float2 v = t[n];
    return make_float2(fmaf(-(float)n, v.y, v.x), v.y);
}

// One pair's 4-element product term: amj has the -0.5 bias pre-folded.
__device__ __forceinline__ float pair_block4(float4 amj, float4 bk,
                                             float shA, float shB) {
    const unsigned FULL = 0xffffffffu;
    float u0 = amj.x - bk.x;
    float u1 = amj.y - bk.y;
    float u2 = amj.z - bk.z;
    float u3 = amj.w - bk.w;
    int z0 = (int)magic_bits(u0);
    int z1 = (int)magic_bits(u1);
    int z2 = (int)magic_bits(u2);
    int z3 = (int)magic_bits(u3);
    float A0 = __shfl_sync(FULL, shA, z0);
    float B0 = __shfl_sync(FULL, shB, z0);
    float A1 = __shfl_sync(FULL, shA, z1);
    float B1 = __shfl_sync(FULL, shB, z1);
    float A2 = __shfl_sync(FULL, shA, z2);
    float B2 = __shfl_sync(FULL, shB, z2);
    float A3 = __shfl_sync(FULL, shA, z3);
    float B3 = __shfl_sync(FULL, shB, z3);
    float e0 = fmaf(u0, B0, A0);
    float e1 = fmaf(u1, B1, A1);
    float e2 = fmaf(u2, B2, A2);
    float e3 = fmaf(u3, B3, A3);
    return (e0 * e1) * (e2 * e3);
}

__global__ __launch_bounds__(NT, 1)
void counter_kernel(const float* __restrict__ boxes,   // (n,4,64)
                    const float* __restrict__ attn,    // (n,64)
                    const float* __restrict__ fw,      // (16,17)
                    float* __restrict__ out)           // (n,11)
{
    extern __shared__ char smem[];
    const int tid  = threadIdx.x;
    const int bi   = blockIdx.x;
    const int lane = tid & 31;
    const int wid  = tid >> 5;
    const unsigned FULL = 0xffffffffu;

    float*  dsT    = (float*)(smem + OFF_DST);
    float*  sim    = (float*)(smem + OFF_SIM);
    float*  Am     = (float*)(smem + OFF_AM);
    float2* tab    = (float2*)(smem + OFF_TAB);
    float*  att_s  = (float*)(smem + OFF_ATT);
    float*  area_s = (float*)(smem + OFF_AREA);
    float*  sbx1   = (float*)(smem + OFF_BX1);
    float*  sby1   = (float*)(smem + OFF_BY1);
    float*  sbx2   = (float*)(smem + OFF_BX2);
    float*  sby2   = (float*)(smem + OFF_BY2);
    float*  part   = (float*)(smem + OFF_PART);
    float*  rowinv = (float*)(smem + OFF_RINV);
    float*  wredA  = (float*)(smem + OFF_WRA);
    float*  wredB  = (float*)(smem + OFF_WRB);

    // Fused address constants for the (cold) packed tables (uint32 wrap).
    const uint32_t lrep = (uint32_t)(tid & 15);
    const uint32_t C2_6 = (OFF_T6  + lrep * 8u  + 128u)  - 0xA0000000u;
    const uint32_t C2_5 = (OFF_T5  + lrep * 8u  + 128u)  - 0xA0000000u;
    const uint32_t C403 = (OFF_T03 + lrep * 16u + 256u)  - 0x40000000u;
    const uint32_t C414 = (OFF_T14 + lrep * 16u + 256u)  - 0x40000000u;

    // ---- Phase 0: serial proven table build (threads 0..7) + input loads ----
    if (tid < 8) {
        const int fn = tid;
        float w[NPW + 1];
        float s = 0.0f;
        #pragma unroll
        for (int i = 0; i <= NPW; i++) { w[i] = fabsf(fw[fn * 17 + i]); s += w[i]; }
        #pragma unroll
        for (int i = 0; i <= NPW; i++) w[i] = w[i] / s;
        float c = 0.0f;
        #pragma unroll
        for (int i = 0; i <= NPW; i++) {
            c += w[i];
            float wn = w[(i + 1 <= NPW) ? (i + 1) : NPW];
            tab[fn * 17 + i] = make_float2(c, wn);
        }
    }
    if (wid >= 8 && wid < 10) {
        const int j = tid - 256;
        att_s[j] = attn[bi * M + j];
        float x1 = boxes[(bi * 4 + 0) * M + j];
        float y1 = boxes[(bi * 4 + 1) * M + j];
        float x2 = boxes[(bi * 4 + 2) * M + j];
        float y2 = boxes[(bi * 4 + 3) * M + j];
        sbx1[j] = x1; sby1[j] = y1; sbx2[j] = x2; sby2[j] = y2;
        area_s[j] = fmaxf(x2 - x1, 0.0f) * fmaxf(y2 - y1, 0.0f);
    }
    __syncthreads();

    // ---- Phase 1a: derive packed, 16x lane-replicated cold tables ----
    if (tid < 19 * 16) {
        const uint32_t slot = (uint32_t)(tid >> 4);
        const uint32_t rep  = (uint32_t)(tid & 15);
        float2 e0 = fused_entry(tab + 0 * 17, slot);
        float2 e3 = fused_entry(tab + 3 * 17, slot);
        *(float4*)(smem + OFF_T03 + slot * 256u + rep * 16u) =
            make_float4(e0.x, 16.0f * e0.y, e3.x, 16.0f * e3.y);
        float2 e1 = fused_entry(tab + 1 * 17, slot);
        float2 e4 = fused_entry(tab + 4 * 17, slot);
        *(float4*)(smem + OFF_T14 + slot * 256u + rep * 16u) =
            make_float4(e1.x, 16.0f * e1.y, e4.x, 16.0f * e4.y);
        float2 e5 = fused_entry(tab + 5 * 17, slot);
        *(float2*)(smem + OFF_T5 + slot * 128u + rep * 8u) =
            make_float2(e5.x, 16.0f * e5.y);
        float2 e6 = fused_entry(tab + 6 * 17, slot);
        *(float2*)(smem + OFF_T6 + slot * 128u + rep * 8u) =
            make_float2(e6.x, 16.0f * e6.y);
        if (rep == 0) {
            float2 e7 = fused_entry(tab + 7 * 17, slot);
            *(float2*)(smem + OFF_T7 + slot * 8u) = make_float2(e7.x, 16.0f * e7.y);
        }
    }

    // ---- Phase 1b: SIGNED-u hot f2 table into warp registers ----
    // e(u) = f2(scaled 1-|u|/16) is continuous piecewise-linear in
    // u = ds_j - ds_k over (-16,16): 32 integer-knot classes m.
    // lane = m mod 32; shuffle index = raw magic bits of u' = u - 0.5.
    float shA, shB;
    {
        int n = (lane < 16) ? (15 - lane) : (lane - 16);
        float2 e2 = fused_entry(tab + 2 * 17, n + 1);
        float U0 = fmaf(16.0f, e2.y, e2.x);       // value at d=0 on segment n
        if (lane < 16) { shA = fmaf(-0.5f, e2.y, U0); shB = -e2.y; }
        else           { shA = fmaf( 0.5f, e2.y, U0); shB =  e2.y; }
    }
    __syncthreads();

    // ---- Phase 2: ds16 (transposed, clamped to [0,16)), Am, dconf, attconf ----
    const int c = tid & 63;
    const int g = tid >> 6;                        // 0..15: 4 rows each
    const float attc = att_s[c];

    float attconf = 0.0f;
    if (tid < M) {
        float x = att_s[tid];
        uint32_t zb = magic_bits(__fmaf_rn(x, 16.0f, -0.5f));
        float2 v = *(const float2*)(smem + (zb * 128u + C2_5));
        attconf = fabsf(fmaf(x, v.y, v.x) - 0.5f);
    }

    float dconf = 0.0f;
    {
        const float x1c = sbx1[c], y1c = sby1[c], x2c = sbx2[c], y2c = sby2[c];
        const float arc = area_s[c];
        #pragma unroll
        for (int it = 0; it < 4; it++) {
            const int r = g + NG * it;
            float rel = att_s[r] * attc;
            uint32_t zb0 = magic_bits(__fmaf_rn(rel, 16.0f, -0.5f));
            float4 v03 = *(const float4*)(smem + (zb0 * 256u + C403));
            float f0v = fmaf(rel, v03.y, v03.x);
            float f3v = fmaf(rel, v03.w, v03.z);

            float ix = fminf(sbx2[r], x2c) - fmaxf(sbx1[r], x1c);
            float iy = fminf(sby2[r], y2c) - fmaxf(sby1[r], y1c);
            ix = fmaxf(ix, 0.0f); iy = fmaxf(iy, 0.0f);
            float inter = ix * iy;
            float den   = area_s[r] + arc - inter + 1e-12f;
            float dist  = 1.0f - inter / den;

            uint32_t zb1 = magic_bits(__fmaf_rn(dist, 16.0f, -0.5f));
            float4 v14 = *(const float4*)(smem + (zb1 * 256u + C414));
            float f1v = fmaf(dist, v14.y, v14.x);
            float f4v = fmaf(dist, v14.w, v14.z);
            float2 v6 = *(const float2*)(smem + (zb1 * 128u + C2_6));
            float f6v = fmaf(dist, v6.y, v6.x);

            float dsv = 16.0f * (f3v * f4v);
            dsv = fminf(fmaxf(dsv, 0.0f), 15.999999f);   // |u| < 16 strictly

            Am[r * M + c]     = f0v * f1v;
            dsT[c * DSTR + r] = dsv;
            dconf += fabsf(f6v - 0.5f);
        }
    }
    __syncthreads();

    // ---- Phase 3: hot m^3 loop; 2x2 block tiling, 17 active warps ----
    // Row pairs: block (jp,kp) with jp<=kp covers rows {2jp,2jp+1}x{2kp,2kp+1}
    // = 4 pairs from 4 row loads. Diagonal blocks' self-pairs evaluate
    // e(0)=csum2[16] every l -> they produce the sim diagonal exactly.
    // Slot count 32*33/2 = 528; warps 17..31 skip (warp-uniform branch).
    if (wid < 17) {
        int p = tid; if (p > NSLOT - 1) p = NSLOT - 1;   // dup tail (16 threads)
        // diagonal-major decode over d = kp-jp: cum(d) = 32d - d(d-1)/2;
        // disc = (65-2d)^2 at boundaries -> __fsqrt_rn exact.
        float s = __fsqrt_rn((float)(4225 - 8 * p));
        int d = (int)((65.0f - s) * 0.5f);
        d = (d < 0) ? 0 : ((d > 31) ? 31 : d);
        int cum = 32 * d - ((d * (d - 1)) >> 1);
        if (p < cum && d > 0) { d--; cum = 32 * d - ((d * (d - 1)) >> 1); }
        if (p - cum >= 32 - d && d < 31) { cum += 32 - d; d++; }
        int i = p - cum;
        i = (i < 0) ? 0 : ((i > 31 - d) ? (31 - d) : i);
        const int jp = i, kp = i + d;
        const int j0 = 2 * jp, j1 = j0 + 1;
        const int k0 = 2 * kp, k1 = k0 + 1;

        const float* pJ = dsT + j0 * DSTR;
        const float* pK = dsT + k0 * DSTR;

        float p00 = 1.0f, p01 = 1.0f, p10 = 1.0f, p11 = 1.0f;

        #pragma unroll 4
        for (int lb = 0; lb < M; lb += 4) {
            float4 aj0 = *(const float4*)(pJ + lb);
            float4 aj1 = *(const float4*)(pJ + DSTR + lb);
            float4 bk0 = *(const float4*)(pK + lb);
            float4 bk1 = *(const float4*)(pK + DSTR + lb);

            // fold the -0.5 magic bias into the j rows (shared by 2 pairs each)
            aj0.x -= 0.5f; aj0.y -= 0.5f; aj0.z -= 0.5f; aj0.w -= 0.5f;
            aj1.x -= 0.5f; aj1.y -= 0.5f; aj1.z -= 0.5f; aj1.w -= 0.5f;

            p00 *= pair_block4(aj0, bk0, shA, shB);
            p01 *= pair_block4(aj0, bk1, shA, shB);
            p10 *= pair_block4(aj1, bk0, shA, shB);
            p11 *= pair_block4(aj1, bk1, shA, shB);
        }

        // att factors + sim writes (4 pairs; mirrors; diag blocks cover
        // the sim diagonal via their self-pairs, e(0) = csum2[16])
        float aj0v = att_s[j0], aj1v = att_s[j1];
        float ak0v = att_s[k0], ak1v = att_s[k1];

        float u00 = __fmaf_rn(16.0f, aj0v - ak0v, -0.5f);
        float u01 = __fmaf_rn(16.0f, aj0v - ak1v, -0.5f);
        float u10 = __fmaf_rn(16.0f, aj1v - ak0v, -0.5f);
        float u11 = __fmaf_rn(16.0f, aj1v - ak1v, -0.5f);
        int z00 = (int)magic_bits(u00);
        int z01 = (int)magic_bits(u01);
        int z10 = (int)magic_bits(u10);
        int z11 = (int)magic_bits(u11);
        float A00 = __shfl_sync(FULL, shA, z00), B00 = __shfl_sync(FULL, shB, z00);
        float A01 = __shfl_sync(FULL, shA, z01), B01 = __shfl_sync(FULL, shB, z01);
        float A10 = __shfl_sync(FULL, shA, z10), B10 = __shfl_sync(FULL, shB, z10);
        float A11 = __shfl_sync(FULL, shA, z11), B11 = __shfl_sync(FULL, shB, z11);
        float s00 = p00 * fmaf(u00, B00, A00);
        float s01 = p01 * fmaf(u01, B01, A01);
        float s10 = p10 * fmaf(u10, B10, A10);
        float s11 = p11 * fmaf(u11, B11, A11);

        sim[j0 * M + k0] = s00; sim[k0 * M + j0] = s00;
        sim[j0 * M + k1] = s01; sim[k1 * M + j0] = s01;
        sim[j1 * M + k0] = s10; sim[k0 * M + j1] = s10;
        sim[j1 * M + k1] = s11; sim[k1 * M + j1] = s11;
    }
    __syncthreads();

    // ---- Phase 4: row sums (column-wise, conflict-free) -> rowinv ----
    {
        float s = 0.0f;
        #pragma unroll
        for (int it = 0; it < 4; it++)
            s += sim[(g + NG * it) * M + c];
        part[g * M + c] = s;
    }
    __syncthreads();
    if (tid < M) {
        float rs = 0.0f;
        #pragma unroll
        for (int gg = 0; gg < NG; gg++) rs += part[gg * M + tid];
        rowinv[tid] = 1.0f / rs;
    }
    __syncthreads();

    // ---- Phase 5: score accumulation (Am reused) ----
    float accA = 0.0f;
    #pragma unroll
    for (int it = 0; it < 4; it++) {
        const int r = g + NG * it;
        accA += Am[r * M + c] * rowinv[r];
    }
    accA *= rowinv[c];

    float corr = 0.0f;
    if (tid < M) {
        float a = att_s[tid];
        float aa = a * a;
        uint32_t zb = magic_bits(__fmaf_rn(aa, 16.0f, -0.5f));
        float4 v03 = *(const float4*)(smem + (zb * 256u + C403));
        corr = fmaf(aa, v03.y, v03.x) * rowinv[tid];
    }

    float ra  = accA + corr;
    float rbv = dconf * (1.0f / 4096.0f) + attconf * (1.0f / 64.0f);
    #pragma unroll
    for (int off = 16; off > 0; off >>= 1) {
        ra  += __shfl_down_sync(FULL, ra,  off);
        rbv += __shfl_down_sync(FULL, rbv, off);
    }
    if (lane == 0) { wredA[wid] = ra; wredB[wid] = rbv; }
    __syncthreads();

    // ---- Phase 6: score -> one-hot * conf ----
    if (tid == 0) {
        float S = 0.0f, B = 0.0f;
        #pragma unroll
        for (int i = 0; i < NW; i++) { S += wredA[i]; B += wredB[i]; }

        float score = sqrtf(S + 1e-20f);
        uint32_t zb = magic_bits(__fmaf_rn(B, 16.0f, -0.5f));
        int slot = (int)(zb - 0x4B3FFFFFu);
        slot = (slot < 0) ? 0 : ((slot > 18) ? 18 : slot);
        float2 v7 = *(const float2*)(smem + OFF_T7 + (uint32_t)slot * 8u);
        float conf = fmaf(B, v7.y, v7.x);

        float sc = fminf(fmaxf(score, 0.0f), (float)OBJ);
        int   i0 = (int)sc;
        float fr = sc - floorf(sc);
        int   i1 = (i0 + 1 <= OBJ) ? (i0 + 1) : OBJ;

        #pragma unroll
        for (int o = 0; o <= OBJ; o++) {
            float v = 0.0f;
            if (o == i0) v += (1.0f - fr);
            if (o == i1) v += fr;
            out[bi * (OBJ + 1) + o] = conf * v;
        }
    }
}

extern "C" void kernel_launch(void* const* d_in, const int* in_sizes, int n_in,
                              void* d_out, int out_size) {
    const float* boxes = (const float*)d_in[0];   // (n,4,64)
    const float* attn  = (const float*)d_in[1];   // (n,64)
    const float* fwts  = (const float*)d_in[2];   // (16,17)
    float* out = (float*)d_out;                   // (n,11)

    cudaFuncSetAttribute(counter_kernel,
                         cudaFuncAttributeMaxDynamicSharedMemorySize, SMEM_TOTAL);

    const int n = in_sizes[1] / M;                // 128
    counter_kernel<<<n, NT, SMEM_TOTAL>>>(boxes, attn, fwts, out);
}

// round 17
// speedup vs baseline: 1.1621x; 1.1621x over previous
#include <cuda_runtime.h>
#include <cuda_bf16.h>
#include <stdint.h>

#define NPW 16
#define M   64
#define NT  1024           // 32 warps, 8/SMSP
#define NW  (NT / 32)
#define NG  16             // row groups for m^2 phases: 16 groups x 4 rows
#define OBJ 10
#define DSTR 68            // dsT row stride (floats)
#define NOFF 496           // 32*31/2 strict off-diagonal 2x2 blocks

#define MAGIC 12582912.0f  // 1.5*2^23; bits(MAGIC + m) = 0x4B400000 + m

// Dynamic shared memory layout (bytes); all offsets 16B-aligned
#define OFF_DST   0u          // dsT[sigma(j)*68 + l], pre-scaled by 16, in [0,16)
#define OFF_SIM   17408u      // (16384)
#define OFF_AM    33792u      // (16384)
#define OFF_T03   50176u      // float4[19*16]  f0 .xy / f3 .zw       (4864)
#define OFF_T14   55040u      // float4[19*16]  f1 .xy / f4 .zw       (4864)
#define OFF_T6    62336u      // float2[19*16]                        (2432)
#define OFF_T5    64768u      // float2[19*16]                        (2432)
#define OFF_T7    67200u      // float2[19] + pad                     (160)
#define OFF_TAB   67360u      // float2[8*17] (csum, w_next)          (1088)
#define OFF_ATT   68448u
#define OFF_AREA  68704u
#define OFF_BX1   68960u
#define OFF_BY1   69216u
#define OFF_BX2   69472u
#define OFF_BY2   69728u
#define OFF_PART  69984u      // NG*64*4 = 4096
#define OFF_RINV  74080u
#define OFF_WRA   74336u      // 32 floats
#define OFF_WRB   74464u      // 32 floats
#define SMEM_TOTAL 74592u

// Protected magic-add: __fadd_rn is never merged/reassociated, so fast-math
// cannot refold bias constants into MAGIC (the R5/R6 bug).
__device__ __forceinline__ uint32_t magic_bits(float t) {
    return __float_as_uint(__fadd_rn(t, MAGIC));
}

// Fused-table entry for slot = n+1 (n = -1..17):
//   val(x) = T0 + (16x)*T1 on segment n, T0 = csum[n] - n*w_next, T1 = w_next.
//   slot 0 (n=-1) encodes the reference's x<0 branch.
__device__ __forceinline__ float2 fused_entry(const float2* __restrict__ t, int slot) {
    if (slot == 0) {
        float cs0 = t[0].x, w1 = t[0].y;
        return make_float2(cs0 + w1, w1);
    }
    int n = slot - 1; if (n > 16) n = 16;
    float2 v = t[n];
    return make_float2(fmaf(-(float)n, v.y, v.x), v.y);
}

// One pair's 4-element product term: amj has the -0.5 bias pre-folded.
__device__ __forceinline__ float pair_block4(float4 amj, float4 bk,
                                             float shA, float shB) {
    const unsigned FULL = 0xffffffffu;
    float u0 = amj.x - bk.x;
    float u1 = amj.y - bk.y;
    float u2 = amj.z - bk.z;
    float u3 = amj.w - bk.w;
    int z0 = (int)magic_bits(u0);
    int z1 = (int)magic_bits(u1);
    int z2 = (int)magic_bits(u2);
    int z3 = (int)magic_bits(u3);
    float A0 = __shfl_sync(FULL, shA, z0);
    float B0 = __shfl_sync(FULL, shB, z0);
    float A1 = __shfl_sync(FULL, shA, z1);
    float B1 = __shfl_sync(FULL, shB, z1);
    float A2 = __shfl_sync(FULL, shA, z2);
    float B2 = __shfl_sync(FULL, shB, z2);
    float A3 = __shfl_sync(FULL, shA, z3);
    float B3 = __shfl_sync(FULL, shB, z3);
    float e0 = fmaf(u0, B0, A0);
    float e1 = fmaf(u1, B1, A1);
    float e2 = fmaf(u2, B2, A2);
    float e3 = fmaf(u3, B3, A3);
    return (e0 * e1) * (e2 * e3);
}

__global__ __launch_bounds__(NT, 1)
void counter_kernel(const float* __restrict__ boxes,   // (n,4,64)
                    const float* __restrict__ attn,    // (n,64)
                    const float* __restrict__ fw,      // (16,17)
                    float* __restrict__ out)           // (n,11)
{
    extern __shared__ char smem[];
    const int tid  = threadIdx.x;
    const int bi   = blockIdx.x;
    const int lane = tid & 31;
    const int wid  = tid >> 5;
    const unsigned FULL = 0xffffffffu;

    float*  dsT    = (float*)(smem + OFF_DST);
    float*  sim    = (float*)(smem + OFF_SIM);
    float*  Am     = (float*)(smem + OFF_AM);
    float2* tab    = (float2*)(smem + OFF_TAB);
    float*  att_s  = (float*)(smem + OFF_ATT);
    float*  area_s = (float*)(smem + OFF_AREA);
    float*  sbx1   = (float*)(smem + OFF_BX1);
    float*  sby1   = (float*)(smem + OFF_BY1);
    float*  sbx2   = (float*)(smem + OFF_BX2);
    float*  sby2   = (float*)(smem + OFF_BY2);
    float*  part   = (float*)(smem + OFF_PART);
    float*  rowinv = (float*)(smem + OFF_RINV);
    float*  wredA  = (float*)(smem + OFF_WRA);
    float*  wredB  = (float*)(smem + OFF_WRB);

    // Fused address constants for the (cold) packed tables (uint32 wrap).
    const uint32_t lrep = (uint32_t)(tid & 15);
    const uint32_t C2_6 = (OFF_T6  + lrep * 8u  + 128u)  - 0xA0000000u;
    const uint32_t C2_5 = (OFF_T5  + lrep * 8u  + 128u)  - 0xA0000000u;
    const uint32_t C403 = (OFF_T03 + lrep * 16u + 256u)  - 0x40000000u;
    const uint32_t C414 = (OFF_T14 + lrep * 16u + 256u)  - 0x40000000u;

    // ---- Phase 0: serial proven table build (threads 0..7) + input loads ----
    if (tid < 8) {
        const int fn = tid;
        float w[NPW + 1];
        float s = 0.0f;
        #pragma unroll
        for (int i = 0; i <= NPW; i++) { w[i] = fabsf(fw[fn * 17 + i]); s += w[i]; }
        #pragma unroll
        for (int i = 0; i <= NPW; i++) w[i] = w[i] / s;
        float c = 0.0f;
        #pragma unroll
        for (int i = 0; i <= NPW; i++) {
            c += w[i];
            float wn = w[(i + 1 <= NPW) ? (i + 1) : NPW];
            tab[fn * 17 + i] = make_float2(c, wn);
        }
    }
    if (wid >= 8 && wid < 10) {
        const int j = tid - 256;
        att_s[j] = attn[bi * M + j];
        float x1 = boxes[(bi * 4 + 0) * M + j];
        float y1 = boxes[(bi * 4 + 1) * M + j];
        float x2 = boxes[(bi * 4 + 2) * M + j];
        float y2 = boxes[(bi * 4 + 3) * M + j];
        sbx1[j] = x1; sby1[j] = y1; sbx2[j] = x2; sby2[j] = y2;
        area_s[j] = fmaxf(x2 - x1, 0.0f) * fmaxf(y2 - y1, 0.0f);
    }
    __syncthreads();

    // ---- Phase 1a: derive packed, 16x lane-replicated cold tables ----
    if (tid < 19 * 16) {
        const uint32_t slot = (uint32_t)(tid >> 4);
        const uint32_t rep  = (uint32_t)(tid & 15);
        float2 e0 = fused_entry(tab + 0 * 17, slot);
        float2 e3 = fused_entry(tab + 3 * 17, slot);
        *(float4*)(smem + OFF_T03 + slot * 256u + rep * 16u) =
            make_float4(e0.x, 16.0f * e0.y, e3.x, 16.0f * e3.y);
        float2 e1 = fused_entry(tab + 1 * 17, slot);
        float2 e4 = fused_entry(tab + 4 * 17, slot);
        *(float4*)(smem + OFF_T14 + slot * 256u + rep * 16u) =
            make_float4(e1.x, 16.0f * e1.y, e4.x, 16.0f * e4.y);
        float2 e5 = fused_entry(tab + 5 * 17, slot);
        *(float2*)(smem + OFF_T5 + slot * 128u + rep * 8u) =
            make_float2(e5.x, 16.0f * e5.y);
        float2 e6 = fused_entry(tab + 6 * 17, slot);
        *(float2*)(smem + OFF_T6 + slot * 128u + rep * 8u) =
            make_float2(e6.x, 16.0f * e6.y);
        if (rep == 0) {
            float2 e7 = fused_entry(tab + 7 * 17, slot);
            *(float2*)(smem + OFF_T7 + slot * 8u) = make_float2(e7.x, 16.0f * e7.y);
        }
    }

    // ---- Phase 1b: SIGNED-u hot f2 table into warp registers ----
    // e(u) = f2(scaled 1-|u|/16): 32 integer-knot classes m over (-16,16).
    // lane = m mod 32; shuffle index = raw magic bits of u' = u - 0.5.
    float shA, shB;
    {
        int n = (lane < 16) ? (15 - lane) : (lane - 16);
        float2 e2 = fused_entry(tab + 2 * 17, n + 1);
        float U0 = fmaf(16.0f, e2.y, e2.x);       // value at d=0 on segment n
        if (lane < 16) { shA = fmaf(-0.5f, e2.y, U0); shB = -e2.y; }
        else           { shA = fmaf( 0.5f, e2.y, U0); shB =  e2.y; }
    }
    __syncthreads();

    // ---- Phase 2: ds16 (row-permuted transposed), Am, dconf, attconf ----
    // dsT row for item-row j lives at slot sigma(j) = (j>>1) + (j&1)*32:
    // even rows in slots 0..31, odd rows in slots 32..63 (2x2 blocks then
    // read 4 lane-consecutive slots -> conflict-free stride-68 loads).
    const int c = tid & 63;
    const int g = tid >> 6;                        // 0..15: 4 rows each
    const float attc = att_s[c];
    const int csl = (c >> 1) + ((c & 1) << 5);     // sigma(c)

    float attconf = 0.0f;
    if (tid < M) {
        float x = att_s[tid];
        uint32_t zb = magic_bits(__fmaf_rn(x, 16.0f, -0.5f));
        float2 v = *(const float2*)(smem + (zb * 128u + C2_5));
        attconf = fabsf(fmaf(x, v.y, v.x) - 0.5f);
    }

    float dconf = 0.0f;
    {
        const float x1c = sbx1[c], y1c = sby1[c], x2c = sbx2[c], y2c = sby2[c];
        const float arc = area_s[c];
        #pragma unroll
        for (int it = 0; it < 4; it++) {
            const int r = g + NG * it;
            float rel = att_s[r] * attc;
            uint32_t zb0 = magic_bits(__fmaf_rn(rel, 16.0f, -0.5f));
            float4 v03 = *(const float4*)(smem + (zb0 * 256u + C403));
            float f0v = fmaf(rel, v03.y, v03.x);
            float f3v = fmaf(rel, v03.w, v03.z);

            float ix = fminf(sbx2[r], x2c) - fmaxf(sbx1[r], x1c);
            float iy = fminf(sby2[r], y2c) - fmaxf(sby1[r], y1c);
            ix = fmaxf(ix, 0.0f); iy = fmaxf(iy, 0.0f);
            float inter = ix * iy;
            float den   = area_s[r] + arc - inter + 1e-12f;
            float dist  = 1.0f - inter / den;

            uint32_t zb1 = magic_bits(__fmaf_rn(dist, 16.0f, -0.5f));
            float4 v14 = *(const float4*)(smem + (zb1 * 256u + C414));
            float f1v = fmaf(dist, v14.y, v14.x);
            float f4v = fmaf(dist, v14.w, v14.z);
            float2 v6 = *(const float2*)(smem + (zb1 * 128u + C2_6));
            float f6v = fmaf(dist, v6.y, v6.x);

            float dsv = 16.0f * (f3v * f4v);
            dsv = fminf(fmaxf(dsv, 0.0f), 15.999999f);   // |u| < 16 strictly

            Am[r * M + c]       = f0v * f1v;
            dsT[csl * DSTR + r] = dsv;
            dconf += fabsf(f6v - 0.5f);
        }
    }
    __syncthreads();

    // ---- Phase 3: hot m^3 loop; 2x2 blocks, l-split halves, 32 warps ----
    if (wid < 31) {
        // Off-diagonal blocks: warp w covers blocks 16w..16w+15 twice;
        // lane<16 computes l in [0,32), lane>=16 computes l in [32,64).
        int b = (wid << 4) + (lane & 15);            // 0..495
        // decode b -> (jp<kp) in 32-triangle: disc=(65-2d)^2 at boundaries
        float s = __fsqrt_rn((float)(3969 - 8 * b));
        int d = (int)((65.0f - s) * 0.5f);
        d = (d < 1) ? 1 : ((d > 31) ? 31 : d);
        int cum = ((d - 1) * (64 - d)) >> 1;
        if (b < cum && d > 1) { d--; cum = ((d - 1) * (64 - d)) >> 1; }
        if (b - cum >= 32 - d && d < 31) { cum += 32 - d; d++; }
        int jp = b - cum;
        jp = (jp < 0) ? 0 : ((jp > 31 - d) ? (31 - d) : jp);
        const int kp = jp + d;

        const int lbase = (lane & 16) << 1;          // 0 or 32
        const float* pJ0 = dsT + jp * DSTR + lbase;         // row 2jp
        const float* pJ1 = dsT + (32 + jp) * DSTR + lbase;   // row 2jp+1
        const float* pK0 = dsT + kp * DSTR + lbase;          // row 2kp
        const float* pK1 = dsT + (32 + kp) * DSTR + lbase;   // row 2kp+1

        float p00 = 1.0f, p01 = 1.0f, p10 = 1.0f, p11 = 1.0f;

        #pragma unroll 4
        for (int lb = 0; lb < 32; lb += 4) {
            float4 aj0 = *(const float4*)(pJ0 + lb);
            float4 aj1 = *(const float4*)(pJ1 + lb);
            float4 bk0 = *(const float4*)(pK0 + lb);
            float4 bk1 = *(const float4*)(pK1 + lb);

            aj0.x -= 0.5f; aj0.y -= 0.5f; aj0.z -= 0.5f; aj0.w -= 0.5f;
            aj1.x -= 0.5f; aj1.y -= 0.5f; aj1.z -= 0.5f; aj1.w -= 0.5f;

            p00 *= pair_block4(aj0, bk0, shA, shB);
            p01 *= pair_block4(aj0, bk1, shA, shB);
            p10 *= pair_block4(aj1, bk0, shA, shB);
            p11 *= pair_block4(aj1, bk1, shA, shB);
        }

        // combine halves (lane l <-> l+16): both end with the full product
        p00 *= __shfl_xor_sync(FULL, p00, 16);
        p01 *= __shfl_xor_sync(FULL, p01, 16);
        p10 *= __shfl_xor_sync(FULL, p10, 16);
        p11 *= __shfl_xor_sync(FULL, p11, 16);

        const int j0 = 2 * jp, j1 = j0 + 1;
        const int k0 = 2 * kp, k1 = k0 + 1;
        float aj0v = att_s[j0], aj1v = att_s[j1];
        float ak0v = att_s[k0], ak1v = att_s[k1];

        float u00 = __fmaf_rn(16.0f, aj0v - ak0v, -0.5f);
        float u01 = __fmaf_rn(16.0f, aj0v - ak1v, -0.5f);
        float u10 = __fmaf_rn(16.0f, aj1v - ak0v, -0.5f);
        float u11 = __fmaf_rn(16.0f, aj1v - ak1v, -0.5f);
        int z00 = (int)magic_bits(u00);
        int z01 = (int)magic_bits(u01);
        int z10 = (int)magic_bits(u10);
        int z11 = (int)magic_bits(u11);
        float A00 = __shfl_sync(FULL, shA, z00), B00 = __shfl_sync(FULL, shB, z00);
        float A01 = __shfl_sync(FULL, shA, z01), B01 = __shfl_sync(FULL, shB, z01);
        float A10 = __shfl_sync(FULL, shA, z10), B10 = __shfl_sync(FULL, shB, z10);
        float A11 = __shfl_sync(FULL, shA, z11), B11 = __shfl_sync(FULL, shB, z11);

        if ((lane & 16) == 0) {
            float s00 = p00 * fmaf(u00, B00, A00);
            float s01 = p01 * fmaf(u01, B01, A01);
            float s10 = p10 * fmaf(u10, B10, A10);
            float s11 = p11 * fmaf(u11, B11, A11);
            sim[j0 * M + k0] = s00; sim[k0 * M + j0] = s00;
            sim[j0 * M + k1] = s01; sim[k1 * M + j0] = s01;
            sim[j1 * M + k0] = s10; sim[k0 * M + j1] = s10;
            sim[j1 * M + k1] = s11; sim[k1 * M + j1] = s11;
        }
    } else {
        // Diagonal warp: lane q handles pair (2q, 2q+1) over full l,
        // plus the two analytic diagonal entries (f2(1)^65 = csum2[16]^65).
        const int q = lane;
        const float* pJ = dsT + q * DSTR;            // row 2q
        const float* pK = dsT + (32 + q) * DSTR;     // row 2q+1

        float pr = 1.0f;
        #pragma unroll 4
        for (int lb = 0; lb < M; lb += 4) {
            float4 aj = *(const float4*)(pJ + lb);
            float4 bk = *(const float4*)(pK + lb);
            aj.x -= 0.5f; aj.y -= 0.5f; aj.z -= 0.5f; aj.w -= 0.5f;
            pr *= pair_block4(aj, bk, shA, shB);
        }

        const int j0 = 2 * q, j1 = j0 + 1;
        float u = __fmaf_rn(16.0f, att_s[j0] - att_s[j1], -0.5f);
        int z = (int)magic_bits(u);
        float A = __shfl_sync(FULL, shA, z), B = __shfl_sync(FULL, shB, z);
        float sv = pr * fmaf(u, B, A);
        sim[j0 * M + j1] = sv;
        sim[j1 * M + j0] = sv;

        float cv = tab[2 * 17 + NPW].x;
        float c2 = cv * cv, c4 = c2 * c2, c8 = c4 * c4;
        float c16 = c8 * c8, c32 = c16 * c16, c64 = c32 * c32;
        float dg = c64 * cv;
        sim[j0 * M + j0] = dg;
        sim[j1 * M + j1] = dg;
    }
    __syncthreads();

    // ---- Phase 4: row sums (column-wise, conflict-free) -> rowinv ----
    {
        float s = 0.0f;
        #pragma unroll
        for (int it = 0; it < 4; it++)
            s += sim[(g + NG * it) * M + c];
        part[g * M + c] = s;
    }
    __syncthreads();
    if (tid < M) {
        float rs = 0.0f;
        #pragma unroll
        for (int gg = 0; gg < NG; gg++) rs += part[gg * M + tid];
        rowinv[tid] = 1.0f / rs;
    }
    __syncthreads();

    // ---- Phase 5: score accumulation (Am reused) ----
    float accA = 0.0f;
    #pragma unroll
    for (int it = 0; it < 4; it++) {
        const int r = g + NG * it;
        accA += Am[r * M + c] * rowinv[r];
    }
    accA *= rowinv[c];

    float corr = 0.0f;
    if (tid < M) {
        float a = att_s[tid];
        float aa = a * a;
        uint32_t zb = magic_bits(__fmaf_rn(aa, 16.0f, -0.5f));
        float4 v03 = *(const float4*)(smem + (zb * 256u + C403));
        corr = fmaf(aa, v03.y, v03.x) * rowinv[tid];
    }

    float ra  = accA + corr;
    float rbv = dconf * (1.0f / 4096.0f) + attconf * (1.0f / 64.0f);
    #pragma unroll
    for (int off = 16; off > 0; off >>= 1) {
        ra  += __shfl_down_sync(FULL, ra,  off);
        rbv += __shfl_down_sync(FULL, rbv, off);
    }
    if (lane == 0) { wredA[wid] = ra; wredB[wid] = rbv; }
    __syncthreads();

    // ---- Phase 6: score -> one-hot * conf ----
    if (tid == 0) {
        float S = 0.0f, B = 0.0f;
        #pragma unroll
        for (int i = 0; i < NW; i++) { S += wredA[i]; B += wredB[i]; }

        float score = sqrtf(S + 1e-20f);
        uint32_t zb = magic_bits(__fmaf_rn(B, 16.0f, -0.5f));
        int slot = (int)(zb - 0x4B3FFFFFu);
        slot = (slot < 0) ? 0 : ((slot > 18) ? 18 : slot);
        float2 v7 = *(const float2*)(smem + OFF_T7 + (uint32_t)slot * 8u);
        float conf = fmaf(B, v7.y, v7.x);

        float sc = fminf(fmaxf(score, 0.0f), (float)OBJ);
        int   i0 = (int)sc;
        float fr = sc - floorf(sc);
        int   i1 = (i0 + 1 <= OBJ) ? (i0 + 1) : OBJ;

        #pragma unroll
        for (int o = 0; o <= OBJ; o++) {
            float v = 0.0f;
            if (o == i0) v += (1.0f - fr);
            if (o == i1) v += fr;
            out[bi * (OBJ + 1) + o] = conf * v;
        }
    }
}

extern "C" void kernel_launch(void* const* d_in, const int* in_sizes, int n_in,
                              void* d_out, int out_size) {
    const float* boxes = (const float*)d_in[0];   // (n,4,64)
    const float* attn  = (const float*)d_in[1];   // (n,64)
    const float* fwts  = (const float*)d_in[2];   // (16,17)
    float* out = (float*)d_out;                   // (n,11)

    cudaFuncSetAttribute(counter_kernel,
                         cudaFuncAttributeMaxDynamicSharedMemorySize, SMEM_TOTAL);

    const int n = in_sizes[1] / M;                // 128
    counter_kernel<<<n, NT, SMEM_TOTAL>>>(boxes, attn, fwts, out);
}